// round 1
// baseline (speedup 1.0000x reference)
#include <cuda_runtime.h>

// Problem constants (fixed by the reference)
#define NN   100000
#define EE   800000
#define D    64
#define CD   256          // (HOPS+1)*D
#define NG   64
#define EMBD 128

// Persistent scratch (no allocations allowed)
__device__ float d_F[(size_t)NN * CD];   // concat features [N][256]
__device__ float d_Y[(size_t)NN * D];    // pre-scaled messages x*deg_norm
__device__ float d_deg[NN];
__device__ float d_dn[NN];               // deg_norm
__device__ float d_gsum[NG * D];

// ---------------------------------------------------------------------------
__global__ void k_zero_dg() {
    int i = blockIdx.x * blockDim.x + threadIdx.x;
    if (i < NN) d_deg[i] = 0.f;
    if (i < NG * D) d_gsum[i] = 0.f;
}

__global__ void k_deg(const int* __restrict__ dst) {
    int e = blockIdx.x * blockDim.x + threadIdx.x;
    if (e < EE) atomicAdd(&d_deg[dst[e]], 1.0f);
}

__global__ void k_dn() {
    int i = blockIdx.x * blockDim.x + threadIdx.x;
    if (i < NN) d_dn[i] = rsqrtf(fmaxf(d_deg[i], 1.0f));
}

// Copy h into F slot0 and produce Y = h * deg_norm
__global__ void k_init(const float* __restrict__ h) {
    int i = blockIdx.x * blockDim.x + threadIdx.x;
    if (i < NN * 16) {
        int r = i >> 4, p = i & 15;
        float4 v = ((const float4*)h)[i];
        ((float4*)d_F)[(size_t)r * 64 + p] = v;
        float dn = d_dn[r];
        ((float4*)d_Y)[i] = make_float4(v.x * dn, v.y * dn, v.z * dn, v.w * dn);
    }
}

// Zero F[:, 64:256] (hop slots 1..3)
__global__ void k_zero_slots() {
    int i = blockIdx.x * blockDim.x + threadIdx.x;
    if (i < NN * 48) {
        int r = i / 48, p = i - r * 48;
        ((float4*)d_F)[(size_t)r * 64 + 16 + p] = make_float4(0.f, 0.f, 0.f, 0.f);
    }
}

// Scatter-add: F[dst][hop*64 + :] += Y[src][:]
__global__ void k_scatter(const int* __restrict__ src, const int* __restrict__ dst, int hop) {
    int i = blockIdx.x * blockDim.x + threadIdx.x;
    if (i < EE * 16) {
        int e = i >> 4, p = i & 15;
        int s = __ldg(src + e);
        int d = __ldg(dst + e);
        float4 v = __ldg((const float4*)d_Y + (size_t)s * 16 + p);
        float* ptr = d_F + (size_t)d * CD + hop * D + p * 4;
        asm volatile("red.global.add.v4.f32 [%0], {%1,%2,%3,%4};"
                     :: "l"(ptr), "f"(v.x), "f"(v.y), "f"(v.z), "f"(v.w) : "memory");
    }
}

// Post-scale hop slot by deg_norm; optionally emit Y for next hop (x * dn^2)
__global__ void k_scale(int hop, int writeY) {
    int i = blockIdx.x * blockDim.x + threadIdx.x;
    if (i < NN * 16) {
        int r = i >> 4, p = i & 15;
        float dn = d_dn[r];
        size_t fi = (size_t)r * 64 + hop * 16 + p;
        float4 v = ((float4*)d_F)[fi];
        v.x *= dn; v.y *= dn; v.z *= dn; v.w *= dn;
        ((float4*)d_F)[fi] = v;
        if (writeY)
            ((float4*)d_Y)[i] = make_float4(v.x * dn, v.y * dn, v.z * dn, v.w * dn);
    }
}

// out[n][c] = relu(sum_j F[n][j] * W[j][c] + b[c])  -> written into F slot0
// also Y[n][c] = out * deg_norm[n] (input for next layer's hop 1)
__global__ void __launch_bounds__(256) k_gemm(const float* __restrict__ W,
                                              const float* __restrict__ b,
                                              int writeY) {
    __shared__ float Xs[64][64];   // [node][j]
    __shared__ float Ws[64][64];   // [j][c]
    int tid = threadIdx.x;
    int tc = tid & 15;             // col group: cols 4*tc..4*tc+3
    int tr = tid >> 4;             // row group: nodes 4*tr..4*tr+3
    int n0 = blockIdx.x * 64;

    float acc[4][4];
#pragma unroll
    for (int m = 0; m < 4; m++)
#pragma unroll
        for (int q = 0; q < 4; q++) acc[m][q] = 0.f;

    for (int kt = 0; kt < 4; kt++) {
#pragma unroll
        for (int i2 = 0; i2 < 4; i2++) {
            int idx = tid + 256 * i2;
            int a = idx >> 4, f4 = idx & 15;
            // X tile: Xs[node][j]
            float4 xv = make_float4(0.f, 0.f, 0.f, 0.f);
            if (n0 + a < NN)
                xv = ((const float4*)d_F)[(size_t)(n0 + a) * 64 + kt * 16 + f4];
            *(float4*)&Xs[a][f4 * 4] = xv;
            // W tile: Ws[j][c]
            float4 wv = ((const float4*)W)[(size_t)(kt * 64 + a) * 16 + f4];
            *(float4*)&Ws[a][f4 * 4] = wv;
        }
        __syncthreads();
#pragma unroll 16
        for (int jj = 0; jj < 64; jj++) {
            float4 w = *(const float4*)&Ws[jj][tc * 4];
            float x0 = Xs[tr * 4 + 0][jj];
            float x1 = Xs[tr * 4 + 1][jj];
            float x2 = Xs[tr * 4 + 2][jj];
            float x3 = Xs[tr * 4 + 3][jj];
            acc[0][0] += x0 * w.x; acc[0][1] += x0 * w.y; acc[0][2] += x0 * w.z; acc[0][3] += x0 * w.w;
            acc[1][0] += x1 * w.x; acc[1][1] += x1 * w.y; acc[1][2] += x1 * w.z; acc[1][3] += x1 * w.w;
            acc[2][0] += x2 * w.x; acc[2][1] += x2 * w.y; acc[2][2] += x2 * w.z; acc[2][3] += x2 * w.w;
            acc[3][0] += x3 * w.x; acc[3][1] += x3 * w.y; acc[3][2] += x3 * w.z; acc[3][3] += x3 * w.w;
        }
        __syncthreads();
    }

    float4 bv = ((const float4*)b)[tc];
#pragma unroll
    for (int m = 0; m < 4; m++) {
        int n = n0 + tr * 4 + m;
        if (n < NN) {
            float4 o;
            o.x = fmaxf(acc[m][0] + bv.x, 0.f);
            o.y = fmaxf(acc[m][1] + bv.y, 0.f);
            o.z = fmaxf(acc[m][2] + bv.z, 0.f);
            o.w = fmaxf(acc[m][3] + bv.w, 0.f);
            ((float4*)d_F)[(size_t)n * 64 + tc] = o;   // slot0 (in-place safe: block-local rows)
            if (writeY) {
                float dn = d_dn[n];
                ((float4*)d_Y)[(size_t)n * 16 + tc] =
                    make_float4(o.x * dn, o.y * dn, o.z * dn, o.w * dn);
            }
        }
    }
}

// Per-graph sums of F slot0; graph_ids sorted -> running-accumulator flush
__global__ void k_gsum(const int* __restrict__ gid) {
    const int CHN = 512;
    int c = threadIdx.x & 63;
    int r0 = threadIdx.x >> 6;
    int nbeg = blockIdx.x * CHN + r0;
    int nend = min(NN, blockIdx.x * CHN + CHN);
    float acc = 0.f;
    int cur = -1;
    for (int n = nbeg; n < nend; n += 4) {
        int g = gid[n];
        if (g != cur) {
            if (cur >= 0) atomicAdd(&d_gsum[cur * D + c], acc);
            cur = g; acc = 0.f;
        }
        acc += d_F[(size_t)n * CD + c];
    }
    if (cur >= 0) atomicAdd(&d_gsum[cur * D + c], acc);
}

// Readout: mean -> @embW + embb -> L2 normalize. One block, 128 threads.
__global__ void k_final(const int* __restrict__ gid,
                        const float* __restrict__ embW,
                        const float* __restrict__ embb,
                        float* __restrict__ out) {
    __shared__ float hg[NG][D];
    __shared__ int bnd[NG + 1];
    __shared__ float nrm[NG];
    int tid = threadIdx.x;

    if (tid <= NG) {
        int lo = 0, hi = NN;                 // first idx with gid[idx] >= tid
        while (lo < hi) {
            int mid = (lo + hi) >> 1;
            if (gid[mid] < tid) lo = mid + 1; else hi = mid;
        }
        bnd[tid] = lo;
    }
    if (tid < NG) nrm[tid] = 0.f;
    __syncthreads();

    for (int idx = tid; idx < NG * D; idx += 128) {
        int g = idx >> 6;
        float cnt = (float)max(bnd[g + 1] - bnd[g], 1);
        hg[g][idx & 63] = d_gsum[idx] / cnt;
    }
    __syncthreads();

    for (int idx = tid; idx < NG * EMBD; idx += 128) {
        int g = idx >> 7, e = idx & 127;
        float s = embb[e];
#pragma unroll 16
        for (int k = 0; k < D; k++) s += hg[g][k] * embW[k * EMBD + e];
        atomicAdd(&nrm[g], s * s);
    }
    __syncthreads();

    for (int idx = tid; idx < NG * EMBD; idx += 128) {
        int g = idx >> 7, e = idx & 127;
        float s = embb[e];
#pragma unroll 16
        for (int k = 0; k < D; k++) s += hg[g][k] * embW[k * EMBD + e];
        float nv = fmaxf(sqrtf(nrm[g]), 1e-12f);
        out[idx] = s / nv;
    }
}

// ---------------------------------------------------------------------------
extern "C" void kernel_launch(void* const* d_in, const int* in_sizes, int n_in,
                              void* d_out, int out_size) {
    const float* h    = (const float*)d_in[0];
    const int*   src  = (const int*)d_in[1];
    const int*   dst  = (const int*)d_in[2];
    const int*   gid  = (const int*)d_in[3];
    const float* Wl[3] = {(const float*)d_in[4], (const float*)d_in[6], (const float*)d_in[8]};
    const float* bl[3] = {(const float*)d_in[5], (const float*)d_in[7], (const float*)d_in[9]};
    const float* embW = (const float*)d_in[10];
    const float* embb = (const float*)d_in[11];
    float* out = (float*)d_out;
    (void)in_sizes; (void)n_in; (void)out_size;

    const int T = 256;
    k_zero_dg<<<(NN + T - 1) / T, T>>>();
    k_deg<<<(EE + T - 1) / T, T>>>(dst);
    k_dn<<<(NN + T - 1) / T, T>>>();
    k_init<<<(NN * 16 + T - 1) / T, T>>>(h);

    for (int L = 0; L < 3; L++) {
        k_zero_slots<<<(NN * 48 + T - 1) / T, T>>>();
        for (int hop = 1; hop <= 3; hop++) {
            k_scatter<<<(EE * 16 + T - 1) / T, T>>>(src, dst, hop);
            k_scale<<<(NN * 16 + T - 1) / T, T>>>(hop, hop < 3 ? 1 : 0);
        }
        k_gemm<<<(NN + 63) / 64, 256>>>(Wl[L], bl[L], 1);
    }

    k_gsum<<<(NN + 511) / 512, 256>>>(gid);
    k_final<<<1, 128>>>(gid, embW, embb, out);
}

// round 2
// speedup vs baseline: 1.2291x; 1.2291x over previous
#include <cuda_runtime.h>

// Problem constants
#define NN   100000
#define EE   800000
#define D    64
#define CD   256          // (HOPS+1)*D
#define NG   64
#define EMBD 128
#define NBLK 391          // ceil(NN/256)

// Persistent scratch (no allocations allowed)
__device__ float d_F[(size_t)NN * CD];    // concat features [N][256]
__device__ float d_Ya[(size_t)NN * D];    // message ping buffer
__device__ float d_Yb[(size_t)NN * D];    // message pong buffer
__device__ int   d_cnt[NN];               // in-degree
__device__ int   d_cur[NN];               // CSR fill cursors
__device__ int   d_off[NN + 1];           // CSR row offsets
__device__ int   d_csr[EE];               // CSR column (src) indices
__device__ int   d_bsum[NBLK];            // scan block sums
__device__ int   d_bpre[NBLK];            // scan block prefixes
__device__ float d_dn[NN];                // deg_norm
__device__ float d_gsum[NG * D];

// ---------------------------------------------------------------------------
// Packed fp32x2 helpers (Blackwell FFMA2)
__device__ __forceinline__ unsigned long long pk2(float x, float y) {
    unsigned long long r;
    asm("mov.b64 %0, {%1,%2};" : "=l"(r) : "f"(x), "f"(y));
    return r;
}
__device__ __forceinline__ void upk2(unsigned long long v, float& lo, float& hi) {
    asm("mov.b64 {%0,%1}, %2;" : "=f"(lo), "=f"(hi) : "l"(v));
}
__device__ __forceinline__ void ffma2(unsigned long long& d, unsigned long long a,
                                      unsigned long long b) {
#if __CUDA_ARCH__ >= 1000
    asm("fma.rn.f32x2 %0, %1, %2, %0;" : "+l"(d) : "l"(a), "l"(b));
#else
    float al, ah, bl, bh, dl, dh;
    upk2(a, al, ah); upk2(b, bl, bh); upk2(d, dl, dh);
    d = pk2(fmaf(al, bl, dl), fmaf(ah, bh, dh));
#endif
}

// ---------------------------------------------------------------------------
__global__ void k_zero() {
    int i = blockIdx.x * blockDim.x + threadIdx.x;
    if (i < NN) { d_cnt[i] = 0; d_cur[i] = 0; }
    if (i < NG * D) d_gsum[i] = 0.f;
}

__global__ void k_count(const int* __restrict__ dst) {
    int e = blockIdx.x * blockDim.x + threadIdx.x;
    if (e < EE) atomicAdd(&d_cnt[dst[e]], 1);
}

__global__ void k_scan_block() {
    __shared__ int s[256];
    int i = blockIdx.x * 256 + threadIdx.x;
    s[threadIdx.x] = (i < NN) ? d_cnt[i] : 0;
    __syncthreads();
    for (int st = 128; st > 0; st >>= 1) {
        if (threadIdx.x < st) s[threadIdx.x] += s[threadIdx.x + st];
        __syncthreads();
    }
    if (threadIdx.x == 0) d_bsum[blockIdx.x] = s[0];
}

__global__ void k_scan_top() {
    __shared__ int s[512];
    int t = threadIdx.x;
    int v = (t < NBLK) ? d_bsum[t] : 0;
    s[t] = v;
    __syncthreads();
    for (int st = 1; st < 512; st <<= 1) {
        int a = (t >= st) ? s[t - st] : 0;
        __syncthreads();
        s[t] += a;
        __syncthreads();
    }
    if (t < NBLK) d_bpre[t] = s[t] - v;   // exclusive prefix
}

__global__ void k_scan_write() {
    __shared__ int s[256];
    int t = threadIdx.x;
    int i = blockIdx.x * 256 + t;
    int v = (i < NN) ? d_cnt[i] : 0;
    s[t] = v;
    __syncthreads();
    for (int st = 1; st < 256; st <<= 1) {
        int a = (t >= st) ? s[t - st] : 0;
        __syncthreads();
        s[t] += a;
        __syncthreads();
    }
    if (i < NN) {
        d_off[i] = d_bpre[blockIdx.x] + s[t] - v;   // exclusive scan
        d_dn[i] = rsqrtf(fmaxf((float)v, 1.0f));
    }
    if (i == 0) d_off[NN] = EE;
}

__global__ void k_fill(const int* __restrict__ src, const int* __restrict__ dst) {
    int e = blockIdx.x * blockDim.x + threadIdx.x;
    if (e < EE) {
        int dd = dst[e];
        int p = atomicAdd(&d_cur[dd], 1);
        d_csr[d_off[dd] + p] = src[e];
    }
}

// F slot0 = h;  Ya = h * deg_norm
__global__ void k_init(const float* __restrict__ h) {
    int i = blockIdx.x * blockDim.x + threadIdx.x;
    if (i < NN * 16) {
        int r = i >> 4, p = i & 15;
        float4 v = ((const float4*)h)[i];
        ((float4*)d_F)[(size_t)r * 64 + p] = v;
        float dn = d_dn[r];
        ((float4*)d_Ya)[i] = make_float4(v.x * dn, v.y * dn, v.z * dn, v.w * dn);
    }
}

// One warp per node: x = dn * sum_{e in in(n)} Yin[src[e]];
// F[n][hop*64+:] = x;  if writeY: Yout[n] = x * dn
__global__ void __launch_bounds__(256) k_hop(int hop, int readB, int writeY) {
    const float* Yin = readB ? d_Yb : d_Ya;
    float* Yout = readB ? d_Ya : d_Yb;
    int n = blockIdx.x * 8 + (threadIdx.x >> 5);   // grid 12500*8 == NN exactly
    int lane = threadIdx.x & 31;
    int e0 = __ldg(d_off + n);
    int e1 = __ldg(d_off + n + 1);
    const float2* Y2 = (const float2*)Yin;
    float2 acc = make_float2(0.f, 0.f);
    int s = (e0 < e1) ? __ldg(d_csr + e0) : 0;
    for (int e = e0; e < e1; e++) {
        int sn = (e + 1 < e1) ? __ldg(d_csr + e + 1) : 0;   // prefetch next index
        float2 v = __ldg(Y2 + (size_t)s * 32 + lane);
        acc.x += v.x; acc.y += v.y;
        s = sn;
    }
    float dn = d_dn[n];
    acc.x *= dn; acc.y *= dn;
    ((float2*)(d_F + (size_t)n * CD + hop * D))[lane] = acc;
    if (writeY)
        ((float2*)Yout)[(size_t)n * 32 + lane] = make_float2(acc.x * dn, acc.y * dn);
}

// out[n][c] = relu(F[n][0:256] @ W + b) -> F slot0; Ya[n] = out * dn (next layer)
// Block: 64 threads, tile 64 nodes x 64 cols, 8x8 per thread via packed FFMA2.
__global__ void __launch_bounds__(64) k_gemm(const float* __restrict__ W,
                                             const float* __restrict__ b) {
    __shared__ float Xs[64][68];   // [node][j], padded
    __shared__ float Ws[64][68];   // [j][c], padded
    int tid = threadIdx.x;
    int trow = tid & 7;            // rows trow + 8r (interleaved -> conflict-free LDS)
    int tcol = tid >> 3;           // cols tcol*8 .. +7
    int n0 = blockIdx.x * 64;

    unsigned long long acc[8][4];
#pragma unroll
    for (int r = 0; r < 8; r++)
#pragma unroll
        for (int p = 0; p < 4; p++) acc[r][p] = 0ull;

    for (int kt = 0; kt < 4; kt++) {
#pragma unroll
        for (int i = 0; i < 16; i++) {
            int fid = tid + 64 * i;
            int a = fid >> 4, f4 = fid & 15;
            float4 xv = make_float4(0.f, 0.f, 0.f, 0.f);
            if (n0 + a < NN)
                xv = ((const float4*)d_F)[(size_t)(n0 + a) * 64 + kt * 16 + f4];
            *(float4*)&Xs[a][f4 * 4] = xv;
            float4 wv = ((const float4*)W)[(size_t)(kt * 64 + a) * 16 + f4];
            *(float4*)&Ws[a][f4 * 4] = wv;
        }
        __syncthreads();
        for (int jj = 0; jj < 64; jj += 4) {
            float4 xv[8];
#pragma unroll
            for (int r = 0; r < 8; r++)
                xv[r] = *(const float4*)&Xs[trow + 8 * r][jj];
#pragma unroll
            for (int j = 0; j < 4; j++) {
                float4 w0 = *(const float4*)&Ws[jj + j][tcol * 8];
                float4 w1 = *(const float4*)&Ws[jj + j][tcol * 8 + 4];
                unsigned long long wp0 = pk2(w0.x, w0.y);
                unsigned long long wp1 = pk2(w0.z, w0.w);
                unsigned long long wp2 = pk2(w1.x, w1.y);
                unsigned long long wp3 = pk2(w1.z, w1.w);
#pragma unroll
                for (int r = 0; r < 8; r++) {
                    float x = (j == 0) ? xv[r].x : (j == 1) ? xv[r].y
                            : (j == 2) ? xv[r].z : xv[r].w;
                    unsigned long long xp = pk2(x, x);
                    ffma2(acc[r][0], xp, wp0);
                    ffma2(acc[r][1], xp, wp1);
                    ffma2(acc[r][2], xp, wp2);
                    ffma2(acc[r][3], xp, wp3);
                }
            }
        }
        __syncthreads();
    }

    float4 b0 = ((const float4*)b)[tcol * 2];
    float4 b1 = ((const float4*)b)[tcol * 2 + 1];
    float bias[8] = {b0.x, b0.y, b0.z, b0.w, b1.x, b1.y, b1.z, b1.w};
#pragma unroll
    for (int r = 0; r < 8; r++) {
        int n = n0 + trow + 8 * r;
        if (n >= NN) continue;
        float o[8];
#pragma unroll
        for (int p = 0; p < 4; p++) upk2(acc[r][p], o[2 * p], o[2 * p + 1]);
#pragma unroll
        for (int c = 0; c < 8; c++) o[c] = fmaxf(o[c] + bias[c], 0.f);
        float4 v0 = make_float4(o[0], o[1], o[2], o[3]);
        float4 v1 = make_float4(o[4], o[5], o[6], o[7]);
        ((float4*)(d_F + (size_t)n * CD))[tcol * 2] = v0;      // slot0
        ((float4*)(d_F + (size_t)n * CD))[tcol * 2 + 1] = v1;
        float dn = d_dn[n];
        ((float4*)(d_Ya + (size_t)n * D))[tcol * 2] =
            make_float4(v0.x * dn, v0.y * dn, v0.z * dn, v0.w * dn);
        ((float4*)(d_Ya + (size_t)n * D))[tcol * 2 + 1] =
            make_float4(v1.x * dn, v1.y * dn, v1.z * dn, v1.w * dn);
    }
}

// Per-graph sums of F slot0 (graph_ids sorted -> running-accumulator flush)
__global__ void k_gsum(const int* __restrict__ gid) {
    const int CHN = 512;
    int c = threadIdx.x & 63;
    int r0 = threadIdx.x >> 6;
    int nbeg = blockIdx.x * CHN + r0;
    int nend = min(NN, blockIdx.x * CHN + CHN);
    float acc = 0.f;
    int cur = -1;
    for (int n = nbeg; n < nend; n += 4) {
        int g = gid[n];
        if (g != cur) {
            if (cur >= 0) atomicAdd(&d_gsum[cur * D + c], acc);
            cur = g; acc = 0.f;
        }
        acc += d_F[(size_t)n * CD + c];
    }
    if (cur >= 0) atomicAdd(&d_gsum[cur * D + c], acc);
}

// Readout: mean -> @embW + embb -> L2 normalize.
__global__ void k_final(const int* __restrict__ gid,
                        const float* __restrict__ embW,
                        const float* __restrict__ embb,
                        float* __restrict__ out) {
    __shared__ float hg[NG][D];
    __shared__ int bnd[NG + 1];
    __shared__ float nrm[NG];
    int tid = threadIdx.x;

    if (tid <= NG) {
        int lo = 0, hi = NN;
        while (lo < hi) {
            int mid = (lo + hi) >> 1;
            if (gid[mid] < tid) lo = mid + 1; else hi = mid;
        }
        bnd[tid] = lo;
    }
    if (tid < NG) nrm[tid] = 0.f;
    __syncthreads();

    for (int idx = tid; idx < NG * D; idx += 128) {
        int g = idx >> 6;
        float cnt = (float)max(bnd[g + 1] - bnd[g], 1);
        hg[g][idx & 63] = d_gsum[idx] / cnt;
    }
    __syncthreads();

    for (int idx = tid; idx < NG * EMBD; idx += 128) {
        int g = idx >> 7, e = idx & 127;
        float s = embb[e];
#pragma unroll 16
        for (int k = 0; k < D; k++) s += hg[g][k] * embW[k * EMBD + e];
        atomicAdd(&nrm[g], s * s);
    }
    __syncthreads();

    for (int idx = tid; idx < NG * EMBD; idx += 128) {
        int g = idx >> 7, e = idx & 127;
        float s = embb[e];
#pragma unroll 16
        for (int k = 0; k < D; k++) s += hg[g][k] * embW[k * EMBD + e];
        float nv = fmaxf(sqrtf(nrm[g]), 1e-12f);
        out[idx] = s / nv;
    }
}

// ---------------------------------------------------------------------------
extern "C" void kernel_launch(void* const* d_in, const int* in_sizes, int n_in,
                              void* d_out, int out_size) {
    const float* h    = (const float*)d_in[0];
    const int*   src  = (const int*)d_in[1];
    const int*   dst  = (const int*)d_in[2];
    const int*   gid  = (const int*)d_in[3];
    const float* Wl[3] = {(const float*)d_in[4], (const float*)d_in[6], (const float*)d_in[8]};
    const float* bl[3] = {(const float*)d_in[5], (const float*)d_in[7], (const float*)d_in[9]};
    const float* embW = (const float*)d_in[10];
    const float* embb = (const float*)d_in[11];
    float* out = (float*)d_out;
    (void)in_sizes; (void)n_in; (void)out_size;

    const int T = 256;
    k_zero<<<(NN + T - 1) / T, T>>>();
    k_count<<<(EE + T - 1) / T, T>>>(dst);
    k_scan_block<<<NBLK, 256>>>();
    k_scan_top<<<1, 512>>>();
    k_scan_write<<<NBLK, 256>>>();
    k_fill<<<(EE + T - 1) / T, T>>>(src, dst);
    k_init<<<(NN * 16 + T - 1) / T, T>>>(h);

    for (int L = 0; L < 3; L++) {
        k_hop<<<12500, 256>>>(1, 0, 1);   // read Ya -> write Yb
        k_hop<<<12500, 256>>>(2, 1, 1);   // read Yb -> write Ya
        k_hop<<<12500, 256>>>(3, 0, 0);   // read Ya
        k_gemm<<<(NN + 63) / 64, 64>>>(Wl[L], bl[L]);   // writes F slot0 + Ya
    }

    k_gsum<<<(NN + 511) / 512, 256>>>(gid);
    k_final<<<1, 128>>>(gid, embW, embb, out);
}